// round 1
// baseline (speedup 1.0000x reference)
#include <cuda_runtime.h>
#include <cuda_bf16.h>

#define N_NODES 100000
#define N_EDGES 1600000
#define IN_CH 128
#define HEADS 4
#define OUT_CH 32
#define HO 128            // HEADS*OUT_CH
#define NEG_SLOPE 0.2f
#define EPS 1e-10f

// ---------------- scratch (no allocations allowed) ----------------
__device__ __align__(16) float g_h[(size_t)N_NODES * HO];      // 51.2 MB
__device__ __align__(16) float g_ssrc[(size_t)N_NODES * HEADS];
__device__ __align__(16) float g_stgt[(size_t)N_NODES * HEADS];
__device__ __align__(16) float g_den[(size_t)N_NODES * HEADS];
__device__ int g_idx64;

// ---------------- dtype detection for edge_index ----------------
// int64 layout with values < 2^31 => every odd 32-bit word is 0.
// int32 layout => odd words are random node ids; P(1024 all zero) ~ 0.
__global__ void detect_kernel(const unsigned int* __restrict__ e) {
    __shared__ int any;
    if (threadIdx.x == 0) any = 0;
    __syncthreads();
    unsigned int v = 0;
    for (int i = threadIdx.x; i < 1024; i += blockDim.x) v |= e[2 * i + 1];
    if (v) any = 1;
    __syncthreads();
    if (threadIdx.x == 0) g_idx64 = (any == 0) ? 1 : 0;
}

// ---------------- zero num (d_out) and den ----------------
__global__ void zero_kernel(float4* __restrict__ out4) {
    int i = blockIdx.x * blockDim.x + threadIdx.x;
    const float4 z = make_float4(0.f, 0.f, 0.f, 0.f);
    if (i < N_NODES * (HO / 4)) out4[i] = z;
    if (i < N_NODES) ((float4*)g_den)[i] = z;
}

// ---------------- GEMM: h = x @ W  (M=100000, N=128, K=128) ----------------
// BM=64 rows/block, 256 threads, BK=32 k-tiles.
// Thread (tx=tid&31, ty=tid>>5): rows ty*8..ty*8+7, cols tx*4..tx*4+3.
#define BM 64
#define BK 32
__global__ __launch_bounds__(256) void gemm_kernel(
    const float* __restrict__ x, const float* __restrict__ W) {
    __shared__ float xs[BM][BK];
    __shared__ float ws[BK][IN_CH];
    const int tid = threadIdx.x;
    const int tx = tid & 31;
    const int ty = tid >> 5;
    const int row0 = blockIdx.x * BM;

    float acc[8][4];
#pragma unroll
    for (int i = 0; i < 8; i++)
#pragma unroll
        for (int j = 0; j < 4; j++) acc[i][j] = 0.f;

    for (int kt = 0; kt < IN_CH / BK; kt++) {
        // load x tile: 64 rows x 32 cols = 512 float4
        for (int i = tid; i < BM * (BK / 4); i += 256) {
            int r = i >> 3;            // /8 float4 per row
            int c4 = i & 7;
            int grow = row0 + r;
            float4 v = make_float4(0.f, 0.f, 0.f, 0.f);
            if (grow < N_NODES)
                v = ((const float4*)x)[(size_t)grow * (IN_CH / 4) + kt * (BK / 4) + c4];
            ((float4*)&xs[r][0])[c4] = v;
        }
        // load W tile: 32 rows x 128 cols = 1024 float4
        for (int i = tid; i < BK * (IN_CH / 4); i += 256) {
            int kr = i >> 5;           // /32 float4 per row
            int c4 = i & 31;
            ((float4*)&ws[kr][0])[c4] =
                ((const float4*)W)[(size_t)(kt * BK + kr) * (IN_CH / 4) + c4];
        }
        __syncthreads();
#pragma unroll
        for (int k = 0; k < BK; k++) {
            float4 w4 = ((const float4*)&ws[k][0])[tx];
#pragma unroll
            for (int i = 0; i < 8; i++) {
                float xv = xs[ty * 8 + i][k];
                acc[i][0] += xv * w4.x;
                acc[i][1] += xv * w4.y;
                acc[i][2] += xv * w4.z;
                acc[i][3] += xv * w4.w;
            }
        }
        __syncthreads();
    }
#pragma unroll
    for (int i = 0; i < 8; i++) {
        int grow = row0 + ty * 8 + i;
        if (grow < N_NODES)
            ((float4*)&g_h[(size_t)grow * HO])[tx] =
                make_float4(acc[i][0], acc[i][1], acc[i][2], acc[i][3]);
    }
}

// ---------------- per-node attention scores ----------------
// warp per node; lane l owns cols 4l..4l+3 (head = l/8).
__global__ __launch_bounds__(256) void score_kernel(const float* __restrict__ att) {
    int warp = (blockIdx.x * blockDim.x + threadIdx.x) >> 5;
    int lane = threadIdx.x & 31;
    if (warp >= N_NODES) return;
    float4 hv = ((const float4*)(g_h + (size_t)warp * HO))[lane];
    int head = lane >> 3;
    int o0 = (lane & 7) * 4;
    const float* arow = att + head * (2 * OUT_CH);
    float ps = hv.x * arow[o0] + hv.y * arow[o0 + 1] +
               hv.z * arow[o0 + 2] + hv.w * arow[o0 + 3];
    float pt = hv.x * arow[OUT_CH + o0] + hv.y * arow[OUT_CH + o0 + 1] +
               hv.z * arow[OUT_CH + o0 + 2] + hv.w * arow[OUT_CH + o0 + 3];
#pragma unroll
    for (int off = 4; off > 0; off >>= 1) {
        ps += __shfl_down_sync(0xffffffffu, ps, off);
        pt += __shfl_down_sync(0xffffffffu, pt, off);
    }
    if ((lane & 7) == 0) {
        g_ssrc[warp * HEADS + head] = ps;
        g_stgt[warp * HEADS + head] = pt;
    }
}

// ---------------- edge scatter: warp per edge ----------------
__global__ __launch_bounds__(256) void edge_kernel(
    const void* __restrict__ eidx, float* __restrict__ out) {
    int warp = (blockIdx.x * blockDim.x + threadIdx.x) >> 5;
    int lane = threadIdx.x & 31;
    if (warp >= N_EDGES) return;
    int src, tgt;
    if (g_idx64) {
        const long long* p = (const long long*)eidx;
        src = (int)p[warp];
        tgt = (int)p[N_EDGES + warp];
    } else {
        const int* p = (const int*)eidx;
        src = p[warp];
        tgt = p[N_EDGES + warp];
    }
    int head = lane >> 3;
    float s = g_ssrc[src * HEADS + head] + g_stgt[tgt * HEADS + head];
    float lr = s > 0.f ? s : NEG_SLOPE * s;
    float w = __expf(-lr);
    float4 hv = ((const float4*)(g_h + (size_t)src * HO))[lane];
    float* orow = out + (size_t)tgt * HO + lane * 4;
    atomicAdd(orow + 0, w * hv.x);
    atomicAdd(orow + 1, w * hv.y);
    atomicAdd(orow + 2, w * hv.z);
    atomicAdd(orow + 3, w * hv.w);
    if ((lane & 7) == 0) atomicAdd(&g_den[tgt * HEADS + head], w);
}

// ---------------- finalize: out = num/clip(den) + bias ----------------
__global__ __launch_bounds__(256) void final_kernel(
    float4* __restrict__ out4, const float4* __restrict__ bias4) {
    int i = blockIdx.x * blockDim.x + threadIdx.x;
    if (i >= N_NODES * (HO / 4)) return;
    int n = i >> 5;          // /32 float4 per row
    int c4 = i & 31;
    int head = c4 >> 3;
    float d = g_den[n * HEADS + head];
    d = d > EPS ? d : EPS;
    float inv = 1.0f / d;
    float4 v = out4[i];
    float4 b = bias4[c4];
    v.x = v.x * inv + b.x;
    v.y = v.y * inv + b.y;
    v.z = v.z * inv + b.z;
    v.w = v.w * inv + b.w;
    out4[i] = v;
}

extern "C" void kernel_launch(void* const* d_in, const int* in_sizes, int n_in,
                              void* d_out, int out_size) {
    const float* x = (const float*)d_in[0];
    const void* eidx = d_in[1];
    const float* W = (const float*)d_in[2];
    const float* att = (const float*)d_in[3];
    const float* bias = (const float*)d_in[4];
    float* out = (float*)d_out;

    detect_kernel<<<1, 256>>>((const unsigned int*)eidx);
    zero_kernel<<<(N_NODES * (HO / 4) + 255) / 256, 256>>>((float4*)out);
    gemm_kernel<<<(N_NODES + BM - 1) / BM, 256>>>(x, W);
    score_kernel<<<(N_NODES * 32 + 255) / 256, 256>>>(att);
    edge_kernel<<<(N_EDGES * 32 + 255) / 256, 256>>>(eidx, out);
    final_kernel<<<(N_NODES * (HO / 4) + 255) / 256, 256>>>((float4*)out,
                                                            (const float4*)bias);
}

// round 2
// speedup vs baseline: 1.6163x; 1.6163x over previous
#include <cuda_runtime.h>
#include <cuda_bf16.h>

#define N_NODES 100000
#define N_EDGES 1600000
#define IN_CH 128
#define HEADS 4
#define OUT_CH 32
#define HO 128            // HEADS*OUT_CH
#define NEG_SLOPE 0.2f
#define EPS 1e-10f

// ---------------- scratch (no allocations allowed) ----------------
__device__ __align__(16) float g_h[(size_t)N_NODES * HO];      // 51.2 MB
__device__ __align__(16) float g_ssrc[(size_t)N_NODES * HEADS];
__device__ __align__(16) float g_stgt[(size_t)N_NODES * HEADS];
__device__ __align__(16) float g_den[(size_t)N_NODES * HEADS];
__device__ int g_idx64;

// ---------------- dtype detection for edge_index ----------------
__global__ void detect_kernel(const unsigned int* __restrict__ e) {
    __shared__ int any;
    if (threadIdx.x == 0) any = 0;
    __syncthreads();
    unsigned int v = 0;
    for (int i = threadIdx.x; i < 1024; i += blockDim.x) v |= e[2 * i + 1];
    if (v) any = 1;
    __syncthreads();
    if (threadIdx.x == 0) g_idx64 = (any == 0) ? 1 : 0;
}

// ---------------- zero num (d_out) and den ----------------
__global__ void zero_kernel(float4* __restrict__ out4) {
    int i = blockIdx.x * blockDim.x + threadIdx.x;
    const float4 z = make_float4(0.f, 0.f, 0.f, 0.f);
    if (i < N_NODES * (HO / 4)) out4[i] = z;
    if (i < N_NODES) ((float4*)g_den)[i] = z;
}

// ---------------- fused GEMM + score kernel ----------------
// h = x @ W  (M=100000, N=128, K=128), f32x2-packed FMA.
// xs tile stored as duplicated pairs {v,v} so LDS.64 yields the packed
// broadcast operand directly. W LDS.128 yields aligned reg pairs for free.
// Epilogue computes s_src/s_tgt per (row, head) via 8-lane group reduce.
#define BM 64
#define BK 32
__global__ __launch_bounds__(256) void gemm_kernel(
    const float* __restrict__ x, const float* __restrict__ W,
    const float* __restrict__ att) {
    __shared__ float2 xs2[BM][BK];    // 16 KB (duplicated pairs)
    __shared__ float ws[BK][IN_CH];   // 16 KB
    const int tid = threadIdx.x;
    const int tx = tid & 31;
    const int ty = tid >> 5;
    const int row0 = blockIdx.x * BM;

    // attention vector slice for this thread's 4 columns
    const int head = tx >> 3;
    const int o0 = (tx & 7) * 4;
    const float* arow = att + head * (2 * OUT_CH);
    float as0 = arow[o0], as1 = arow[o0 + 1], as2 = arow[o0 + 2], as3 = arow[o0 + 3];
    float at0 = arow[OUT_CH + o0], at1 = arow[OUT_CH + o0 + 1],
          at2 = arow[OUT_CH + o0 + 2], at3 = arow[OUT_CH + o0 + 3];

    unsigned long long acc[8][2];
#pragma unroll
    for (int i = 0; i < 8; i++) { acc[i][0] = 0ull; acc[i][1] = 0ull; }

    for (int kt = 0; kt < IN_CH / BK; kt++) {
        // load x tile: 64 rows x 32 cols, write each value duplicated
        for (int i = tid; i < BM * (BK / 4); i += 256) {
            int r = i >> 3;
            int c4 = (i & 7) * 4;
            int grow = row0 + r;
            float4 v = make_float4(0.f, 0.f, 0.f, 0.f);
            if (grow < N_NODES)
                v = ((const float4*)x)[(size_t)grow * (IN_CH / 4) + kt * 8 + (i & 7)];
            xs2[r][c4 + 0] = make_float2(v.x, v.x);
            xs2[r][c4 + 1] = make_float2(v.y, v.y);
            xs2[r][c4 + 2] = make_float2(v.z, v.z);
            xs2[r][c4 + 3] = make_float2(v.w, v.w);
        }
        // load W tile: 32 rows x 128 cols
        for (int i = tid; i < BK * (IN_CH / 4); i += 256) {
            int kr = i >> 5;
            int c4 = i & 31;
            ((float4*)&ws[kr][0])[c4] =
                ((const float4*)W)[(size_t)(kt * BK + kr) * (IN_CH / 4) + c4];
        }
        __syncthreads();
#pragma unroll
        for (int k = 0; k < BK; k++) {
            float4 w4 = ((const float4*)&ws[k][0])[tx];
            unsigned long long w01, w23;
            asm("mov.b64 %0, {%1, %2};" : "=l"(w01) : "f"(w4.x), "f"(w4.y));
            asm("mov.b64 %0, {%1, %2};" : "=l"(w23) : "f"(w4.z), "f"(w4.w));
#pragma unroll
            for (int i = 0; i < 8; i++) {
                unsigned long long xv2 =
                    *reinterpret_cast<const unsigned long long*>(&xs2[ty * 8 + i][k]);
                asm("fma.rn.f32x2 %0, %1, %2, %0;" : "+l"(acc[i][0]) : "l"(xv2), "l"(w01));
                asm("fma.rn.f32x2 %0, %1, %2, %0;" : "+l"(acc[i][1]) : "l"(xv2), "l"(w23));
            }
        }
        __syncthreads();
    }

    // epilogue: write h + fused per-head scores
#pragma unroll
    for (int i = 0; i < 8; i++) {
        int grow = row0 + ty * 8 + i;
        float c0, c1, c2, c3;
        asm("mov.b64 {%0, %1}, %2;" : "=f"(c0), "=f"(c1) : "l"(acc[i][0]));
        asm("mov.b64 {%0, %1}, %2;" : "=f"(c2), "=f"(c3) : "l"(acc[i][1]));
        if (grow < N_NODES)
            ((float4*)&g_h[(size_t)grow * HO])[tx] = make_float4(c0, c1, c2, c3);
        float ps = c0 * as0 + c1 * as1 + c2 * as2 + c3 * as3;
        float pt = c0 * at0 + c1 * at1 + c2 * at2 + c3 * at3;
        // reduce within 8-lane group (one head per group)
#pragma unroll
        for (int off = 4; off > 0; off >>= 1) {
            ps += __shfl_xor_sync(0xffffffffu, ps, off);
            pt += __shfl_xor_sync(0xffffffffu, pt, off);
        }
        if ((tx & 7) == 0 && grow < N_NODES) {
            g_ssrc[grow * HEADS + head] = ps;
            g_stgt[grow * HEADS + head] = pt;
        }
    }
}

// ---------------- edge scatter: warp per edge, vector RED ----------------
__global__ __launch_bounds__(256) void edge_kernel(
    const void* __restrict__ eidx, float* __restrict__ out) {
    int warp = (blockIdx.x * blockDim.x + threadIdx.x) >> 5;
    int lane = threadIdx.x & 31;
    if (warp >= N_EDGES) return;
    int src, tgt;
    if (g_idx64) {
        const long long* p = (const long long*)eidx;
        src = (int)p[warp];
        tgt = (int)p[N_EDGES + warp];
    } else {
        const int* p = (const int*)eidx;
        src = p[warp];
        tgt = p[N_EDGES + warp];
    }
    int head = lane >> 3;
    float s = g_ssrc[src * HEADS + head] + g_stgt[tgt * HEADS + head];
    float lr = s > 0.f ? s : NEG_SLOPE * s;
    float w = __expf(-lr);
    float4 hv = ((const float4*)(g_h + (size_t)src * HO))[lane];
    float* orow = out + (size_t)tgt * HO + lane * 4;
    asm volatile("red.global.add.v4.f32 [%0], {%1, %2, %3, %4};"
                 :: "l"(orow), "f"(w * hv.x), "f"(w * hv.y),
                    "f"(w * hv.z), "f"(w * hv.w)
                 : "memory");
    if ((lane & 7) == 0) atomicAdd(&g_den[tgt * HEADS + head], w);
}

// ---------------- finalize: out = num/clip(den) + bias ----------------
__global__ __launch_bounds__(256) void final_kernel(
    float4* __restrict__ out4, const float4* __restrict__ bias4) {
    int i = blockIdx.x * blockDim.x + threadIdx.x;
    if (i >= N_NODES * (HO / 4)) return;
    int n = i >> 5;
    int c4 = i & 31;
    int head = c4 >> 3;
    float d = g_den[n * HEADS + head];
    d = d > EPS ? d : EPS;
    float inv = 1.0f / d;
    float4 v = out4[i];
    float4 b = bias4[c4];
    v.x = v.x * inv + b.x;
    v.y = v.y * inv + b.y;
    v.z = v.z * inv + b.z;
    v.w = v.w * inv + b.w;
    out4[i] = v;
}

extern "C" void kernel_launch(void* const* d_in, const int* in_sizes, int n_in,
                              void* d_out, int out_size) {
    const float* x = (const float*)d_in[0];
    const void* eidx = d_in[1];
    const float* W = (const float*)d_in[2];
    const float* att = (const float*)d_in[3];
    const float* bias = (const float*)d_in[4];
    float* out = (float*)d_out;

    detect_kernel<<<1, 256>>>((const unsigned int*)eidx);
    zero_kernel<<<(N_NODES * (HO / 4) + 255) / 256, 256>>>((float4*)out);
    gemm_kernel<<<(N_NODES + BM - 1) / BM, 256>>>(x, W, att);
    edge_kernel<<<(N_EDGES * 32 + 255) / 256, 256>>>(eidx, out);
    final_kernel<<<(N_NODES * (HO / 4) + 255) / 256, 256>>>((float4*)out,
                                                            (const float4*)bias);
}

// round 3
// speedup vs baseline: 2.5724x; 1.5916x over previous
#include <cuda_runtime.h>
#include <cuda_bf16.h>

#define N_NODES 100000
#define N_EDGES 1600000
#define IN_CH 128
#define HEADS 4
#define OUT_CH 32
#define HO 128
#define NEG_SLOPE 0.2f
#define EPS 1e-10f

#define SCAN_B 512
#define SCAN_NB ((N_NODES + SCAN_B - 1) / SCAN_B)   // 196

// ---------------- scratch ----------------
__device__ __align__(16) float g_h[(size_t)N_NODES * HO];      // 51.2 MB
__device__ __align__(16) float g_ssrc[(size_t)N_NODES * HEADS];
__device__ __align__(16) float g_stgt[(size_t)N_NODES * HEADS];
__device__ int g_deg[N_NODES];
__device__ int g_off[N_NODES];
__device__ int g_cursor[N_NODES];
__device__ int g_bsum[SCAN_NB];
__device__ int g_esrc[N_EDGES];
__device__ int g_idx64;

// ---------------- dtype detection for edge_index ----------------
__global__ void detect_kernel(const unsigned int* __restrict__ e) {
    __shared__ int any;
    if (threadIdx.x == 0) any = 0;
    __syncthreads();
    unsigned int v = 0;
    for (int i = threadIdx.x; i < 1024; i += blockDim.x) v |= e[2 * i + 1];
    if (v) any = 1;
    __syncthreads();
    if (threadIdx.x == 0) g_idx64 = (any == 0) ? 1 : 0;
}

__device__ __forceinline__ int load_idx(const void* eidx, int i) {
    if (g_idx64) return (int)((const long long*)eidx)[i];
    return ((const int*)eidx)[i];
}

// ---------------- zero degree histogram ----------------
__global__ void zero_deg_kernel() {
    int i = blockIdx.x * blockDim.x + threadIdx.x;
    if (i < N_NODES) g_deg[i] = 0;
}

// ---------------- histogram of targets ----------------
__global__ __launch_bounds__(256) void hist_kernel(const void* __restrict__ eidx) {
    int e = blockIdx.x * blockDim.x + threadIdx.x;
    if (e >= N_EDGES) return;
    int tgt = load_idx(eidx, N_EDGES + e);
    atomicAdd(&g_deg[tgt], 1);
}

// ---------------- 3-phase exclusive scan of g_deg -> g_off ----------------
__global__ __launch_bounds__(SCAN_B) void scan1_kernel() {
    __shared__ int sm[SCAN_B];
    int i = blockIdx.x * SCAN_B + threadIdx.x;
    int t = threadIdx.x;
    int v = (i < N_NODES) ? g_deg[i] : 0;
    sm[t] = v;
    __syncthreads();
#pragma unroll
    for (int off = 1; off < SCAN_B; off <<= 1) {
        int a = (t >= off) ? sm[t - off] : 0;
        __syncthreads();
        sm[t] += a;
        __syncthreads();
    }
    if (i < N_NODES) g_off[i] = sm[t] - v;         // exclusive within block
    if (t == SCAN_B - 1) g_bsum[blockIdx.x] = sm[t];
}

__global__ __launch_bounds__(256) void scan2_kernel() {
    __shared__ int sm[256];
    int t = threadIdx.x;
    int v = (t < SCAN_NB) ? g_bsum[t] : 0;
    sm[t] = v;
    __syncthreads();
#pragma unroll
    for (int off = 1; off < 256; off <<= 1) {
        int a = (t >= off) ? sm[t - off] : 0;
        __syncthreads();
        sm[t] += a;
        __syncthreads();
    }
    if (t < SCAN_NB) g_bsum[t] = sm[t] - v;        // exclusive block offsets
}

__global__ __launch_bounds__(SCAN_B) void scan3_kernel() {
    int i = blockIdx.x * SCAN_B + threadIdx.x;
    if (i >= N_NODES) return;
    int o = g_off[i] + g_bsum[blockIdx.x];
    g_off[i] = o;
    g_cursor[i] = o;
}

// ---------------- scatter edges into CSR buckets ----------------
__global__ __launch_bounds__(256) void scatter_kernel(const void* __restrict__ eidx) {
    int e = blockIdx.x * blockDim.x + threadIdx.x;
    if (e >= N_EDGES) return;
    int src = load_idx(eidx, e);
    int tgt = load_idx(eidx, N_EDGES + e);
    int slot = atomicAdd(&g_cursor[tgt], 1);
    g_esrc[slot] = src;
}

// ---------------- fused GEMM + score kernel ----------------
#define BM 64
#define BK 32
__global__ __launch_bounds__(256) void gemm_kernel(
    const float* __restrict__ x, const float* __restrict__ W,
    const float* __restrict__ att) {
    __shared__ float2 xs2[BM][BK];
    __shared__ float ws[BK][IN_CH];
    const int tid = threadIdx.x;
    const int tx = tid & 31;
    const int ty = tid >> 5;
    const int row0 = blockIdx.x * BM;

    const int head = tx >> 3;
    const int o0 = (tx & 7) * 4;
    const float* arow = att + head * (2 * OUT_CH);
    float as0 = arow[o0], as1 = arow[o0 + 1], as2 = arow[o0 + 2], as3 = arow[o0 + 3];
    float at0 = arow[OUT_CH + o0], at1 = arow[OUT_CH + o0 + 1],
          at2 = arow[OUT_CH + o0 + 2], at3 = arow[OUT_CH + o0 + 3];

    unsigned long long acc[8][2];
#pragma unroll
    for (int i = 0; i < 8; i++) { acc[i][0] = 0ull; acc[i][1] = 0ull; }

    for (int kt = 0; kt < IN_CH / BK; kt++) {
        for (int i = tid; i < BM * (BK / 4); i += 256) {
            int r = i >> 3;
            int c4 = (i & 7) * 4;
            int grow = row0 + r;
            float4 v = make_float4(0.f, 0.f, 0.f, 0.f);
            if (grow < N_NODES)
                v = ((const float4*)x)[(size_t)grow * (IN_CH / 4) + kt * 8 + (i & 7)];
            xs2[r][c4 + 0] = make_float2(v.x, v.x);
            xs2[r][c4 + 1] = make_float2(v.y, v.y);
            xs2[r][c4 + 2] = make_float2(v.z, v.z);
            xs2[r][c4 + 3] = make_float2(v.w, v.w);
        }
        for (int i = tid; i < BK * (IN_CH / 4); i += 256) {
            int kr = i >> 5;
            int c4 = i & 31;
            ((float4*)&ws[kr][0])[c4] =
                ((const float4*)W)[(size_t)(kt * BK + kr) * (IN_CH / 4) + c4];
        }
        __syncthreads();
#pragma unroll
        for (int k = 0; k < BK; k++) {
            float4 w4 = ((const float4*)&ws[k][0])[tx];
            unsigned long long w01, w23;
            asm("mov.b64 %0, {%1, %2};" : "=l"(w01) : "f"(w4.x), "f"(w4.y));
            asm("mov.b64 %0, {%1, %2};" : "=l"(w23) : "f"(w4.z), "f"(w4.w));
#pragma unroll
            for (int i = 0; i < 8; i++) {
                unsigned long long xv2 =
                    *reinterpret_cast<const unsigned long long*>(&xs2[ty * 8 + i][k]);
                asm("fma.rn.f32x2 %0, %1, %2, %0;" : "+l"(acc[i][0]) : "l"(xv2), "l"(w01));
                asm("fma.rn.f32x2 %0, %1, %2, %0;" : "+l"(acc[i][1]) : "l"(xv2), "l"(w23));
            }
        }
        __syncthreads();
    }

#pragma unroll
    for (int i = 0; i < 8; i++) {
        int grow = row0 + ty * 8 + i;
        float c0, c1, c2, c3;
        asm("mov.b64 {%0, %1}, %2;" : "=f"(c0), "=f"(c1) : "l"(acc[i][0]));
        asm("mov.b64 {%0, %1}, %2;" : "=f"(c2), "=f"(c3) : "l"(acc[i][1]));
        if (grow < N_NODES)
            ((float4*)&g_h[(size_t)grow * HO])[tx] = make_float4(c0, c1, c2, c3);
        float ps = c0 * as0 + c1 * as1 + c2 * as2 + c3 * as3;
        float pt = c0 * at0 + c1 * at1 + c2 * at2 + c3 * at3;
#pragma unroll
        for (int off = 4; off > 0; off >>= 1) {
            ps += __shfl_xor_sync(0xffffffffu, ps, off);
            pt += __shfl_xor_sync(0xffffffffu, pt, off);
        }
        if ((tx & 7) == 0 && grow < N_NODES) {
            g_ssrc[grow * HEADS + head] = ps;
            g_stgt[grow * HEADS + head] = pt;
        }
    }
}

// ---------------- gather-reduce: warp per node, fused finalize ----------------
// Within an 8-lane head group, w is identical for every lane -> no reductions.
__global__ __launch_bounds__(256) void gather_kernel(
    float* __restrict__ out, const float* __restrict__ bias) {
    int node = (blockIdx.x * blockDim.x + threadIdx.x) >> 5;
    int lane = threadIdx.x & 31;
    if (node >= N_NODES) return;
    int head = lane >> 3;

    int start = g_off[node];
    int cnt = g_deg[node];
    float st = g_stgt[node * HEADS + head];

    float4 acc = make_float4(0.f, 0.f, 0.f, 0.f);
    float den = 0.f;

    int j = 0;
    for (; j + 2 <= cnt; j += 2) {
        int s0 = g_esrc[start + j];
        int s1 = g_esrc[start + j + 1];
        float sc0 = g_ssrc[s0 * HEADS + head] + st;
        float sc1 = g_ssrc[s1 * HEADS + head] + st;
        float4 h0 = ((const float4*)(g_h + (size_t)s0 * HO))[lane];
        float4 h1 = ((const float4*)(g_h + (size_t)s1 * HO))[lane];
        float lr0 = sc0 > 0.f ? sc0 : NEG_SLOPE * sc0;
        float lr1 = sc1 > 0.f ? sc1 : NEG_SLOPE * sc1;
        float w0 = __expf(-lr0);
        float w1 = __expf(-lr1);
        acc.x += w0 * h0.x + w1 * h1.x;
        acc.y += w0 * h0.y + w1 * h1.y;
        acc.z += w0 * h0.z + w1 * h1.z;
        acc.w += w0 * h0.w + w1 * h1.w;
        den += w0 + w1;
    }
    if (j < cnt) {
        int s0 = g_esrc[start + j];
        float sc0 = g_ssrc[s0 * HEADS + head] + st;
        float4 h0 = ((const float4*)(g_h + (size_t)s0 * HO))[lane];
        float lr0 = sc0 > 0.f ? sc0 : NEG_SLOPE * sc0;
        float w0 = __expf(-lr0);
        acc.x += w0 * h0.x;
        acc.y += w0 * h0.y;
        acc.z += w0 * h0.z;
        acc.w += w0 * h0.w;
        den += w0;
    }

    float d = den > EPS ? den : EPS;
    float inv = 1.0f / d;
    float4 b = ((const float4*)bias)[lane];
    float4 o;
    o.x = acc.x * inv + b.x;
    o.y = acc.y * inv + b.y;
    o.z = acc.z * inv + b.z;
    o.w = acc.w * inv + b.w;
    ((float4*)(out + (size_t)node * HO))[lane] = o;
}

extern "C" void kernel_launch(void* const* d_in, const int* in_sizes, int n_in,
                              void* d_out, int out_size) {
    const float* x = (const float*)d_in[0];
    const void* eidx = d_in[1];
    const float* W = (const float*)d_in[2];
    const float* att = (const float*)d_in[3];
    const float* bias = (const float*)d_in[4];
    float* out = (float*)d_out;

    detect_kernel<<<1, 256>>>((const unsigned int*)eidx);
    zero_deg_kernel<<<(N_NODES + 255) / 256, 256>>>();
    hist_kernel<<<(N_EDGES + 255) / 256, 256>>>(eidx);
    scan1_kernel<<<SCAN_NB, SCAN_B>>>();
    scan2_kernel<<<1, 256>>>();
    scan3_kernel<<<SCAN_NB, SCAN_B>>>();
    scatter_kernel<<<(N_EDGES + 255) / 256, 256>>>(eidx);
    gemm_kernel<<<(N_NODES + BM - 1) / BM, 256>>>(x, W, att);
    gather_kernel<<<(N_NODES * 32 + 255) / 256, 256>>>(out, bias);
}